// round 8
// baseline (speedup 1.0000x reference)
#include <cuda_runtime.h>
#include <cuda_fp16.h>

#define NG    20000
#define BATCH 128
#define UNITS 10000
#define DEG   32

// Scratch: |feature| transposed to [gene][batch] in fp16 (5.12 MB).
// 256 B per gene row. Device global = sanctioned allocation-free scratch.
__device__ __half g_featT[(size_t)NG * BATCH];

// ---------------------------------------------------------------------------
// Kernel 1: featT[g][b] = (half)|feature[b][g]|
// One block = 32 genes x ALL 128 batches, so gene-row writes are full,
// perfectly coalesced 256 B stores. Reads: 16 independent coalesced LDG.32
// per thread (MLP=16). Convert to half during the SMEM staging write.
// SMEM row stride = 132 halves (264 B): 8 B-aligned rows for uint2 reads;
// staging writes are at worst 2-way conflicted (negligible).
// ---------------------------------------------------------------------------
__global__ __launch_bounds__(256) void transpose_abs_kernel(const float* __restrict__ f) {
    __shared__ __half ht[32 * 132];          // [gene][batch(+pad)]
    const int g0 = blockIdx.x * 32;          // NG = 625*32, exact
    const int x  = threadIdx.x;              // 0..31  (gene within tile)
    const int y  = threadIdx.y;              // 0..7

    // Load + abs + convert. Warp reads 128 B coalesced per iteration.
#pragma unroll
    for (int i = 0; i < 16; i++) {
        int b = i * 8 + y;                   // 0..127
        float v = fabsf(__ldg(&f[(size_t)b * NG + g0 + x]));
        ht[x * 132 + b] = __float2half(v);
    }
    __syncthreads();

    // Store: 1024 uint2 chunks (32 rows x 32 chunks); warp = one 256 B row.
    const int t = threadIdx.y * 32 + threadIdx.x;
#pragma unroll
    for (int k = 0; k < 4; k++) {
        int c  = t + 256 * k;
        int gl = c >> 5;
        int ln = c & 31;
        uint2 v = *(const uint2*)&ht[gl * 132 + ln * 4];
        *(uint2*)&g_featT[(size_t)(g0 + gl) * BATCH + ln * 4] = v;
    }
}

// Fast tanh: 1 - 2*rcp(1 + ex2(2*log2e * x)).  ~5 instr, ~1e-6 rel err.
// Saturates correctly at +/-1 for large |x| (inf -> rcp=0; 0 -> 1-2 = -1).
__device__ __forceinline__ float fast_tanh(float x) {
    float e, r;
    asm("ex2.approx.f32 %0, %1;" : "=f"(e) : "f"(x * 2.88539008177793f));
    float s = 1.0f + e;
    asm("rcp.approx.f32 %0, %1;" : "=f"(r) : "f"(s));
    return fmaf(-2.0f, r, 1.0f);
}

// ---------------------------------------------------------------------------
// Kernel 2: gather + reduce + epilogue.
// One warp per unit; lane d holds ppi[u][d] (int32). Genes broadcast by shfl
// in PAIRS: the two gene rows' half2 values are summed with HADD2 in fp16
// first (error ~2^-11 * mag, tanh-squashed), halving convert+add count.
// Warp load per gene = 256 B fully coalesced (uint2 per lane).
// ---------------------------------------------------------------------------
__global__ __launch_bounds__(256) void gather_kernel(
    const int*   __restrict__ ppi,
    const float* __restrict__ kern,
    const float* __restrict__ bias,
    float*       __restrict__ out)
{
    __shared__ float so[8 * 129];            // [warp][batch], padded

    const int w    = threadIdx.x >> 5;
    const int lane = threadIdx.x & 31;
    const int u    = blockIdx.x * 8 + w;     // UNITS = 1250*8, always valid

    // Lane d owns neighbor d; precompute its byte offset into featT.
    int off = __ldg(&ppi[(size_t)u * DEG + lane]) << 8;   // gene * 256 B

    const char* base = (const char*)g_featT + lane * 8;   // lane's 8 B slice
    float a0 = 0.f, a1 = 0.f, a2 = 0.f, a3 = 0.f;

#pragma unroll
    for (int d = 0; d < DEG; d += 2) {
        int oA = __shfl_sync(0xffffffffu, off, d);
        int oB = __shfl_sync(0xffffffffu, off, d + 1);
        uint2 rA = *(const uint2*)(base + oA);
        uint2 rB = *(const uint2*)(base + oB);
        __half2 s0 = __hadd2(*(const __half2*)&rA.x, *(const __half2*)&rB.x);
        __half2 s1 = __hadd2(*(const __half2*)&rA.y, *(const __half2*)&rB.y);
        float2 f0 = __half22float2(s0);
        float2 f1 = __half22float2(s1);
        a0 += f0.x; a1 += f0.y; a2 += f1.x; a3 += f1.y;
    }

    const float k  = __ldg(&kern[u]);
    const float bi = __ldg(&bias[u]);
    const int   b0 = lane * 4;

    so[w * 129 + b0 + 0] = fast_tanh(fmaf(a0, k, bi));
    so[w * 129 + b0 + 1] = fast_tanh(fmaf(a1, k, bi));
    so[w * 129 + b0 + 2] = fast_tanh(fmaf(a2, k, bi));
    so[w * 129 + b0 + 3] = fast_tanh(fmaf(a3, k, bi));

    __syncthreads();

    // Coalesced writeback: batch rows x 8 consecutive units.
    const int u0 = blockIdx.x * 8;
#pragma unroll
    for (int i = threadIdx.x; i < BATCH * 8; i += 256) {
        int b = i >> 3;
        int j = i & 7;
        out[(size_t)b * UNITS + u0 + j] = so[j * 129 + b];
    }
}

// ---------------------------------------------------------------------------
extern "C" void kernel_launch(void* const* d_in, const int* in_sizes, int n_in,
                              void* d_out, int out_size)
{
    (void)in_sizes; (void)n_in; (void)out_size;
    const float* feature = (const float*)d_in[0];
    const int*   ppi     = (const int*)d_in[1];
    const float* kern    = (const float*)d_in[2];
    const float* bias    = (const float*)d_in[3];
    float*       out     = (float*)d_out;

    transpose_abs_kernel<<<NG / 32, dim3(32, 8)>>>(feature);
    gather_kernel<<<UNITS / 8, 256>>>(ppi, kern, bias, out);
}

// round 9
// speedup vs baseline: 1.1994x; 1.1994x over previous
#include <cuda_runtime.h>
#include <cuda_fp16.h>

#define NG    20000
#define BATCH 128
#define UNITS 10000
#define DEG   32

// Scratch: |feature| transposed to [gene][batch] in fp16 (5.12 MB, fits L2).
__device__ __half g_featT[(size_t)NG * BATCH];

// ---------------------------------------------------------------------------
// Kernel 1: featT[g][b] = (half)|feature[b][g]| — EXACT round-7 version
// (empirically 4.0 us; the round-8 rewrite regressed to ~14 us).
// ---------------------------------------------------------------------------
__global__ __launch_bounds__(256) void transpose_abs_kernel(const float* __restrict__ f) {
    __shared__ float tile[32][33];
    const int g0 = blockIdx.x * 32;
    const int b0 = blockIdx.y * 32;
    const int x = threadIdx.x;   // 0..31
    const int y = threadIdx.y;   // 0..7

#pragma unroll
    for (int i = 0; i < 32; i += 8) {
        int g = g0 + x;
        int b = b0 + y + i;
        float v = 0.0f;
        if (g < NG) v = fabsf(f[(size_t)b * NG + g]);
        tile[y + i][x] = v;
    }
    __syncthreads();
#pragma unroll
    for (int i = 0; i < 32; i += 8) {
        int g = g0 + y + i;
        int b = b0 + x;
        if (g < NG)
            g_featT[(size_t)g * BATCH + b] = __float2half(tile[x][y + i]);
    }
}

// Fast tanh: 1 - 2*rcp(1 + ex2(2*log2e*x)). ~5 instr, ~1e-6 rel err,
// saturates correctly at +/-1.
__device__ __forceinline__ float fast_tanh(float x) {
    float e, r;
    asm("ex2.approx.f32 %0, %1;" : "=f"(e) : "f"(x * 2.88539008177793f));
    float s = 1.0f + e;
    asm("rcp.approx.f32 %0, %1;" : "=f"(r) : "f"(s));
    return fmaf(-2.0f, r, 1.0f);
}

__device__ __forceinline__ __half2 h2(unsigned int v) { return *(__half2*)&v; }

// ---------------------------------------------------------------------------
// Kernel 2: gather + reduce + epilogue.
// One warp per unit. All 8 units' ppi offsets staged in SMEM (one coalesced
// 1KB load); loop reads them via broadcast LDS.128 (no SHFL, no dependency
// chain). 8 independent LDG.64 per iteration (explicit MLP=8), fp16 tree
// reduction over gene quads, fp32 accumulation across quads.
// ---------------------------------------------------------------------------
__global__ __launch_bounds__(256) void gather_kernel(
    const int*   __restrict__ ppi,
    const float* __restrict__ kern,
    const float* __restrict__ bias,
    float*       __restrict__ out)
{
    __shared__ int   offs[256];      // [unit-in-block][deg] -> gene*32 (uint2 idx)
    __shared__ float so[8 * 129];    // [warp][batch], padded

    const int tid  = threadIdx.x;
    const int w    = tid >> 5;
    const int lane = tid & 31;
    const int u0   = blockIdx.x * 8;          // UNITS = 1250*8

    // ppi rows for units u0..u0+7 are contiguous: 256 ints, one coalesced load.
    offs[tid] = __ldg(&ppi[(size_t)u0 * DEG + tid]) << 5;   // gene * 32 uint2
    __syncthreads();

    const uint2* ft = (const uint2*)g_featT;  // gene row = 32 x uint2 (256 B)
    const int*   wo = &offs[w * 32];
    float a0 = 0.f, a1 = 0.f, a2 = 0.f, a3 = 0.f;

#pragma unroll
    for (int grp = 0; grp < DEG; grp += 8) {
        int4 oA = *(const int4*)&wo[grp];     // broadcast LDS.128
        int4 oB = *(const int4*)&wo[grp + 4];
        uint2 r0 = __ldg(&ft[oA.x + lane]);   // 8 independent LDG.64
        uint2 r1 = __ldg(&ft[oA.y + lane]);
        uint2 r2 = __ldg(&ft[oA.z + lane]);
        uint2 r3 = __ldg(&ft[oA.w + lane]);
        uint2 r4 = __ldg(&ft[oB.x + lane]);
        uint2 r5 = __ldg(&ft[oB.y + lane]);
        uint2 r6 = __ldg(&ft[oB.z + lane]);
        uint2 r7 = __ldg(&ft[oB.w + lane]);

        // fp16 tree over gene quads (values >= 0, mag <= ~4: safe in fp16).
        __half2 sx0 = __hadd2(__hadd2(h2(r0.x), h2(r1.x)), __hadd2(h2(r2.x), h2(r3.x)));
        __half2 sy0 = __hadd2(__hadd2(h2(r0.y), h2(r1.y)), __hadd2(h2(r2.y), h2(r3.y)));
        __half2 sx1 = __hadd2(__hadd2(h2(r4.x), h2(r5.x)), __hadd2(h2(r6.x), h2(r7.x)));
        __half2 sy1 = __hadd2(__hadd2(h2(r4.y), h2(r5.y)), __hadd2(h2(r6.y), h2(r7.y)));

        float2 f;
        f = __half22float2(sx0); a0 += f.x; a1 += f.y;
        f = __half22float2(sy0); a2 += f.x; a3 += f.y;
        f = __half22float2(sx1); a0 += f.x; a1 += f.y;
        f = __half22float2(sy1); a2 += f.x; a3 += f.y;
    }

    const int u  = u0 + w;
    const float k  = __ldg(&kern[u]);
    const float bi = __ldg(&bias[u]);
    const int   b0 = lane * 4;

    so[w * 129 + b0 + 0] = fast_tanh(fmaf(a0, k, bi));
    so[w * 129 + b0 + 1] = fast_tanh(fmaf(a1, k, bi));
    so[w * 129 + b0 + 2] = fast_tanh(fmaf(a2, k, bi));
    so[w * 129 + b0 + 3] = fast_tanh(fmaf(a3, k, bi));

    __syncthreads();

    // Coalesced writeback: batch rows x 8 consecutive units.
#pragma unroll
    for (int i = tid; i < BATCH * 8; i += 256) {
        int b = i >> 3;
        int j = i & 7;
        out[(size_t)b * UNITS + u0 + j] = so[j * 129 + b];
    }
}

// ---------------------------------------------------------------------------
extern "C" void kernel_launch(void* const* d_in, const int* in_sizes, int n_in,
                              void* d_out, int out_size)
{
    (void)in_sizes; (void)n_in; (void)out_size;
    const float* feature = (const float*)d_in[0];
    const int*   ppi     = (const int*)d_in[1];
    const float* kern    = (const float*)d_in[2];
    const float* bias    = (const float*)d_in[3];
    float*       out     = (float*)d_out;

    dim3 tblock(32, 8);
    dim3 tgrid((NG + 31) / 32, BATCH / 32);
    transpose_abs_kernel<<<tgrid, tblock>>>(feature);

    gather_kernel<<<UNITS / 8, 256>>>(ppi, kern, bias, out);
}

// round 11
// speedup vs baseline: 1.4757x; 1.2303x over previous
#include <cuda_runtime.h>
#include <cuda_fp16.h>
#include <cstdint>

#define NG    20000
#define BATCH 128
#define UNITS 10000
#define DEG   32

// Scratch: |feature| transposed to [gene][batch] in fp16 (5.12 MB, fits L2).
// 256 B per gene row, 256 B aligned so bulk-copy sources are 16 B aligned.
__device__ __align__(256) __half g_featT[(size_t)NG * BATCH];

// ---------------------------------------------------------------------------
// Kernel 1: featT[g][b] = (half)|feature[b][g]| — EXACT round-7 version
// (measured 4.0 us; the round-8 rewrite regressed, keep this one).
// ---------------------------------------------------------------------------
__global__ __launch_bounds__(256) void transpose_abs_kernel(const float* __restrict__ f) {
    __shared__ float tile[32][33];
    const int g0 = blockIdx.x * 32;
    const int b0 = blockIdx.y * 32;
    const int x = threadIdx.x;
    const int y = threadIdx.y;

#pragma unroll
    for (int i = 0; i < 32; i += 8) {
        int g = g0 + x;
        int b = b0 + y + i;
        float v = 0.0f;
        if (g < NG) v = fabsf(f[(size_t)b * NG + g]);
        tile[y + i][x] = v;
    }
    __syncthreads();
#pragma unroll
    for (int i = 0; i < 32; i += 8) {
        int g = g0 + y + i;
        int b = b0 + x;
        if (g < NG)
            g_featT[(size_t)g * BATCH + b] = __float2half(tile[x][y + i]);
    }
}

// Fast tanh: 1 - 2*rcp(1 + ex2(2*log2e*x)). ~5 instr, ~1e-6 rel err,
// saturates correctly at +/-1.
__device__ __forceinline__ float fast_tanh(float x) {
    float e, r;
    asm("ex2.approx.f32 %0, %1;" : "=f"(e) : "f"(x * 2.88539008177793f));
    float s = 1.0f + e;
    asm("rcp.approx.f32 %0, %1;" : "=f"(r) : "f"(s));
    return fmaf(-2.0f, r, 1.0f);
}

__device__ __forceinline__ __half2 h2(unsigned int v) { return *(__half2*)&v; }

// SMEM layout (dynamic): 8 warps x 32 rows x 256 B, then so[8*129] f32, then 8 mbarriers.
#define ROWS_BYTES   (8 * DEG * 256)                 // 65536
#define SO_OFF       ROWS_BYTES                      // 65536
#define MBAR_OFF     (SO_OFF + 8 * 129 * 4)          // 69664
#define SMEM_TOTAL   (MBAR_OFF + 8 * 8)              // 69728

// ---------------------------------------------------------------------------
// Kernel 2: async-bulk gather + SMEM reduce + epilogue.
// One warp per unit. Each lane issues cp.async.bulk of its gene's 256 B row
// (GMEM->SMEM, L2-hit) to the warp's 8 KB slab; one mbarrier per warp with
// expect_tx = 8192. No LDGs in the hot path -> no scoreboard/L1tex-queue
// limits on outstanding demand; ~24 warps/SM x 8 KB in flight drives L2
// toward its throughput ceiling. Reduce from SMEM with conflict-free LDS.64
// and the fp16 quad-tree (fp32 across quads).
// ---------------------------------------------------------------------------
__global__ __launch_bounds__(256) void gather_kernel(
    const int*   __restrict__ ppi,
    const float* __restrict__ kern,
    const float* __restrict__ bias,
    float*       __restrict__ out)
{
    extern __shared__ __align__(16) char smem[];
    uint32_t sbase;
    asm("{ .reg .u64 t; cvta.to.shared.u64 t, %1; cvt.u32.u64 %0, t; }"
        : "=r"(sbase) : "l"(smem));

    const int tid  = threadIdx.x;
    const int w    = tid >> 5;
    const int lane = tid & 31;
    const int u0   = blockIdx.x * 8;          // UNITS = 1250*8
    const int u    = u0 + w;

    // Init one mbarrier per warp (arrive count 1 = the expect_tx arrive).
    if (tid < 8) {
        asm volatile("mbarrier.init.shared.b64 [%0], 1;"
                     :: "r"(sbase + MBAR_OFF + tid * 8) : "memory");
    }
    __syncthreads();

    const uint32_t mbar = sbase + MBAR_OFF + w * 8;

    // Lane d owns neighbor d. Coalesced 128 B ppi read per warp.
    int gene = __ldg(&ppi[(size_t)u * DEG + lane]);
    uint64_t src = (uint64_t)__cvta_generic_to_global(g_featT) + ((uint64_t)gene << 8);
    uint32_t dst = sbase + w * (DEG * 256) + lane * 256;

    if (lane == 0) {
        asm volatile("mbarrier.arrive.expect_tx.shared.b64 _, [%0], %1;"
                     :: "r"(mbar), "r"(DEG * 256) : "memory");
    }
    __syncwarp();
    asm volatile("cp.async.bulk.shared::cta.global.mbarrier::complete_tx::bytes "
                 "[%0], [%1], %2, [%3];"
                 :: "r"(dst), "l"(src), "r"(256), "r"(mbar) : "memory");

    // Wait for all 32 rows (phase parity 0; kernel runs once per replay).
    asm volatile(
        "{\n\t.reg .pred P;\n\t"
        "WL_%=: mbarrier.try_wait.parity.acquire.cta.shared::cta.b64 P, [%0], 0;\n\t"
        "@P bra WD_%=;\n\t"
        "bra WL_%=;\n\t"
        "WD_%=:\n\t}"
        :: "r"(mbar) : "memory");

    // Reduce 32 rows from SMEM: fp16 tree over gene quads, fp32 across quads.
    const char* rw = smem + w * (DEG * 256);
    float a0 = 0.f, a1 = 0.f, a2 = 0.f, a3 = 0.f;

#pragma unroll
    for (int grp = 0; grp < DEG; grp += 8) {
        uint2 r0 = *(const uint2*)(rw + (grp + 0) * 256 + lane * 8);
        uint2 r1 = *(const uint2*)(rw + (grp + 1) * 256 + lane * 8);
        uint2 r2 = *(const uint2*)(rw + (grp + 2) * 256 + lane * 8);
        uint2 r3 = *(const uint2*)(rw + (grp + 3) * 256 + lane * 8);
        uint2 r4 = *(const uint2*)(rw + (grp + 4) * 256 + lane * 8);
        uint2 r5 = *(const uint2*)(rw + (grp + 5) * 256 + lane * 8);
        uint2 r6 = *(const uint2*)(rw + (grp + 6) * 256 + lane * 8);
        uint2 r7 = *(const uint2*)(rw + (grp + 7) * 256 + lane * 8);

        __half2 sx0 = __hadd2(__hadd2(h2(r0.x), h2(r1.x)), __hadd2(h2(r2.x), h2(r3.x)));
        __half2 sy0 = __hadd2(__hadd2(h2(r0.y), h2(r1.y)), __hadd2(h2(r2.y), h2(r3.y)));
        __half2 sx1 = __hadd2(__hadd2(h2(r4.x), h2(r5.x)), __hadd2(h2(r6.x), h2(r7.x)));
        __half2 sy1 = __hadd2(__hadd2(h2(r4.y), h2(r5.y)), __hadd2(h2(r6.y), h2(r7.y)));

        float2 f;
        f = __half22float2(sx0); a0 += f.x; a1 += f.y;
        f = __half22float2(sy0); a2 += f.x; a3 += f.y;
        f = __half22float2(sx1); a0 += f.x; a1 += f.y;
        f = __half22float2(sy1); a2 += f.x; a3 += f.y;
    }

    const float k  = __ldg(&kern[u]);
    const float bi = __ldg(&bias[u]);
    const int   b0 = lane * 4;
    float* so = (float*)(smem + SO_OFF);

    so[w * 129 + b0 + 0] = fast_tanh(fmaf(a0, k, bi));
    so[w * 129 + b0 + 1] = fast_tanh(fmaf(a1, k, bi));
    so[w * 129 + b0 + 2] = fast_tanh(fmaf(a2, k, bi));
    so[w * 129 + b0 + 3] = fast_tanh(fmaf(a3, k, bi));

    __syncthreads();

    // Coalesced writeback: batch rows x 8 consecutive units (32 B runs).
#pragma unroll
    for (int i = tid; i < BATCH * 8; i += 256) {
        int b = i >> 3;
        int j = i & 7;
        out[(size_t)b * UNITS + u0 + j] = so[j * 129 + b];
    }
}

// ---------------------------------------------------------------------------
extern "C" void kernel_launch(void* const* d_in, const int* in_sizes, int n_in,
                              void* d_out, int out_size)
{
    (void)in_sizes; (void)n_in; (void)out_size;
    const float* feature = (const float*)d_in[0];
    const int*   ppi     = (const int*)d_in[1];
    const float* kern    = (const float*)d_in[2];
    const float* bias    = (const float*)d_in[3];
    float*       out     = (float*)d_out;

    // Opt in to >48KB dynamic SMEM (host-side attribute set, not an alloc;
    // idempotent and capture-safe).
    static bool attr_done = false;
    if (!attr_done) {
        cudaFuncSetAttribute(gather_kernel,
                             cudaFuncAttributeMaxDynamicSharedMemorySize, SMEM_TOTAL);
        attr_done = true;
    }

    dim3 tblock(32, 8);
    dim3 tgrid((NG + 31) / 32, BATCH / 32);
    transpose_abs_kernel<<<tgrid, tblock>>>(feature);

    gather_kernel<<<UNITS / 8, 256, SMEM_TOTAL>>>(ppi, kern, bias, out);
}

// round 15
// speedup vs baseline: 1.6983x; 1.1509x over previous
#include <cuda_runtime.h>
#include <cuda_fp16.h>

#define NG    20000
#define BATCH 128
#define UNITS 10000
#define DEG   32

// Scratch: |feature| transposed to [gene][batch] in fp16 (5.12 MB, fits L2).
__device__ __align__(256) __half g_featT[(size_t)NG * BATCH];

// ---------------------------------------------------------------------------
// Kernel 1: featT[g][b] = (half)|feature[b][g]| — EXACT round-7 version
// (measured 4.0 us; both rewrites regressed, keep it).
// ---------------------------------------------------------------------------
__global__ __launch_bounds__(256) void transpose_abs_kernel(const float* __restrict__ f) {
    __shared__ float tile[32][33];
    const int g0 = blockIdx.x * 32;
    const int b0 = blockIdx.y * 32;
    const int x = threadIdx.x;
    const int y = threadIdx.y;

#pragma unroll
    for (int i = 0; i < 32; i += 8) {
        int g = g0 + x;
        int b = b0 + y + i;
        float v = 0.0f;
        if (g < NG) v = fabsf(f[(size_t)b * NG + g]);
        tile[y + i][x] = v;
    }
    __syncthreads();
#pragma unroll
    for (int i = 0; i < 32; i += 8) {
        int g = g0 + y + i;
        int b = b0 + x;
        if (g < NG)
            g_featT[(size_t)g * BATCH + b] = __float2half(tile[x][y + i]);
    }
}

// Fast tanh: 1 - 2*rcp(1 + ex2(2*log2e*x)). ~5 instr, ~1e-6 rel err,
// saturates correctly at +/-1.
__device__ __forceinline__ float fast_tanh(float x) {
    float e, r;
    asm("ex2.approx.f32 %0, %1;" : "=f"(e) : "f"(x * 2.88539008177793f));
    float s = 1.0f + e;
    asm("rcp.approx.f32 %0, %1;" : "=f"(r) : "f"(s));
    return fmaf(-2.0f, r, 1.0f);
}

__device__ __forceinline__ __half2 h2(unsigned int v) { return *(__half2*)&v; }

// ---------------------------------------------------------------------------
// Kernel 2: gather + reduce + epilogue (r8 structure + 4-gene fp16 tree +
// explicit depth-1 software pipeline: next 4 gene-row loads are issued
// BEFORE the current group's reduce, so LDG latency overlaps ALU work).
// One warp per unit; lane d holds ppi[u][d]; shfl-broadcast offsets.
// Warp load per gene = 256 B fully coalesced (uint2 per lane).
// ---------------------------------------------------------------------------
__global__ __launch_bounds__(256) void gather_kernel(
    const int*   __restrict__ ppi,
    const float* __restrict__ kern,
    const float* __restrict__ bias,
    float*       __restrict__ out)
{
    __shared__ float so[8 * 129];            // [warp][batch], padded

    const int w    = threadIdx.x >> 5;
    const int lane = threadIdx.x & 31;
    const int u0   = blockIdx.x * 8;         // UNITS = 1250*8
    const int u    = u0 + w;

    // Lane d owns neighbor d; byte offset of its gene row.
    int off = __ldg(&ppi[(size_t)u * DEG + lane]) << 8;

    const char* base = (const char*)g_featT + lane * 8;   // lane's 8 B slice
    float a0 = 0.f, a1 = 0.f, a2 = 0.f, a3 = 0.f;

    // Prologue: load group 0 (genes 0..3).
    int p0 = __shfl_sync(0xffffffffu, off, 0);
    int p1 = __shfl_sync(0xffffffffu, off, 1);
    int p2 = __shfl_sync(0xffffffffu, off, 2);
    int p3 = __shfl_sync(0xffffffffu, off, 3);
    uint2 rA = *(const uint2*)(base + p0);
    uint2 rB = *(const uint2*)(base + p1);
    uint2 rC = *(const uint2*)(base + p2);
    uint2 rD = *(const uint2*)(base + p3);

#pragma unroll
    for (int d = 4; d < DEG; d += 4) {
        // Prefetch next group before consuming current one.
        int n0 = __shfl_sync(0xffffffffu, off, d);
        int n1 = __shfl_sync(0xffffffffu, off, d + 1);
        int n2 = __shfl_sync(0xffffffffu, off, d + 2);
        int n3 = __shfl_sync(0xffffffffu, off, d + 3);
        uint2 nA = *(const uint2*)(base + n0);
        uint2 nB = *(const uint2*)(base + n1);
        uint2 nC = *(const uint2*)(base + n2);
        uint2 nD = *(const uint2*)(base + n3);

        // 4-gene fp16 tree (values >= 0, sum <= ~16: safe in fp16;
        // measured rel_err 2.0e-5 with this tree in round 9).
        __half2 q0 = __hadd2(__hadd2(h2(rA.x), h2(rB.x)), __hadd2(h2(rC.x), h2(rD.x)));
        __half2 q1 = __hadd2(__hadd2(h2(rA.y), h2(rB.y)), __hadd2(h2(rC.y), h2(rD.y)));
        float2 f0 = __half22float2(q0);
        float2 f1 = __half22float2(q1);
        a0 += f0.x; a1 += f0.y; a2 += f1.x; a3 += f1.y;

        rA = nA; rB = nB; rC = nC; rD = nD;
    }

    // Epilogue group (genes 28..31).
    {
        __half2 q0 = __hadd2(__hadd2(h2(rA.x), h2(rB.x)), __hadd2(h2(rC.x), h2(rD.x)));
        __half2 q1 = __hadd2(__hadd2(h2(rA.y), h2(rB.y)), __hadd2(h2(rC.y), h2(rD.y)));
        float2 f0 = __half22float2(q0);
        float2 f1 = __half22float2(q1);
        a0 += f0.x; a1 += f0.y; a2 += f1.x; a3 += f1.y;
    }

    const float k  = __ldg(&kern[u]);
    const float bi = __ldg(&bias[u]);
    const int   b0 = lane * 4;

    so[w * 129 + b0 + 0] = fast_tanh(fmaf(a0, k, bi));
    so[w * 129 + b0 + 1] = fast_tanh(fmaf(a1, k, bi));
    so[w * 129 + b0 + 2] = fast_tanh(fmaf(a2, k, bi));
    so[w * 129 + b0 + 3] = fast_tanh(fmaf(a3, k, bi));

    __syncthreads();

    // Coalesced writeback: batch rows x 8 consecutive units (32 B runs).
#pragma unroll
    for (int i = threadIdx.x; i < BATCH * 8; i += 256) {
        int b = i >> 3;
        int j = i & 7;
        out[(size_t)b * UNITS + u0 + j] = so[j * 129 + b];
    }
}

// ---------------------------------------------------------------------------
extern "C" void kernel_launch(void* const* d_in, const int* in_sizes, int n_in,
                              void* d_out, int out_size)
{
    (void)in_sizes; (void)n_in; (void)out_size;
    const float* feature = (const float*)d_in[0];
    const int*   ppi     = (const int*)d_in[1];
    const float* kern    = (const float*)d_in[2];
    const float* bias    = (const float*)d_in[3];
    float*       out     = (float*)d_out;

    dim3 tblock(32, 8);
    dim3 tgrid((NG + 31) / 32, BATCH / 32);
    transpose_abs_kernel<<<tgrid, tblock>>>(feature);

    gather_kernel<<<UNITS / 8, 256>>>(ppi, kern, bias, out);
}